// round 7
// baseline (speedup 1.0000x reference)
#include <cuda_runtime.h>
#include <cuda_bf16.h>
#include <cstdint>

#define BATCH 2
#define RDIM  64
#define CDIM  2048
#define EDIM  128
#define HEADS 4
#define DHEAD 32
#define NROWS (BATCH*RDIM*CDIM)      // 262144
#define NBR   (BATCH*RDIM)           // 128
#define NCTA  (NROWS/128)            // 2048
#define GSIZE 16                     // CTAs per (b,r) group
#define PART_STRIDE 4224             // 4*32*32 ktv + 128 ksum floats per CTA

#define PITCH 136                    // bf16 elements per row (MMA tiles)
#define QP    132                    // fp32 q staging pitch (conflict-free)

typedef unsigned int u32;

// Scratch (device globals)
__device__ float g_ksum[(size_t)NBR * HEADS * DHEAD];
__device__ __align__(16) float g_part[(size_t)NCTA * PART_STRIDE];
__device__ __align__(16) __nv_bfloat16 g_G[NBR][2][128 * PITCH];
__device__ __align__(16) __nv_bfloat16 g_wt[3][2][128 * PITCH];
__device__ int g_ctr[NBR];
__device__ int g_flag[NBR];

__device__ __forceinline__ float elu1(float x) {
    return x > 0.f ? x + 1.f : expf(x);
}

__device__ __forceinline__ void mma16816(float* d, const u32* a, u32 b0, u32 b1) {
    asm volatile(
        "mma.sync.aligned.m16n8k16.row.col.f32.bf16.bf16.f32 "
        "{%0,%1,%2,%3}, {%4,%5,%6,%7}, {%8,%9}, {%0,%1,%2,%3};"
        : "+f"(d[0]), "+f"(d[1]), "+f"(d[2]), "+f"(d[3])
        : "r"(a[0]), "r"(a[1]), "r"(a[2]), "r"(a[3]), "r"(b0), "r"(b1));
}

__device__ __forceinline__ void ldsm_x4_t(u32* r, u32 addr) {
    asm volatile("ldmatrix.sync.aligned.m8n8.x4.trans.shared.b16 {%0,%1,%2,%3}, [%4];"
        : "=r"(r[0]), "=r"(r[1]), "=r"(r[2]), "=r"(r[3]) : "r"(addr));
}

__device__ __forceinline__ uint32_t smem_u32(const void* p) {
    uint32_t a;
    asm("{ .reg .u64 t; cvta.to.shared.u64 t, %1; cvt.u32.u64 %0, t; }" : "=r"(a) : "l"(p));
    return a;
}

__device__ __forceinline__ u32 pack_bf2(float x, float y) {
    __nv_bfloat162 p = __floats2bfloat162_rn(x, y);
    return *(u32*)&p;
}

__device__ __forceinline__ int atom_add_acqrel(int* p) {
    int o;
    asm volatile("atom.add.acq_rel.gpu.s32 %0, [%1], 1;" : "=r"(o) : "l"(p) : "memory");
    return o;
}
__device__ __forceinline__ void st_release(int* p, int v) {
    asm volatile("st.release.gpu.s32 [%0], %1;" :: "l"(p), "r"(v) : "memory");
}
__device__ __forceinline__ int ld_acquire(int* p) {
    int v;
    asm volatile("ld.acquire.gpu.s32 %0, [%1];" : "=r"(v) : "l"(p) : "memory");
    return v;
}

// 3-pass split GEMM block (proven): K=128, smem [r][k] bf16 pitch PITCH.
template <int NT>
__device__ __forceinline__ void gemm3p(
    const char* sa_hi, const char* sa_lo,
    const char* sb_hi, const char* sb_lo,
    int arow, int ncol0, int lane, float acc[NT][4])
{
    const int g = lane >> 2, c = lane & 3;
#pragma unroll
    for (int k0 = 0; k0 < 128; k0 += 16) {
        const int e0 = ((arow + g) * PITCH + k0 + 2 * c) * 2;
        const int e1 = ((arow + g + 8) * PITCH + k0 + 2 * c) * 2;
        u32 ah[4], al[4];
        ah[0] = *(const u32*)(sa_hi + e0);
        ah[1] = *(const u32*)(sa_hi + e1);
        ah[2] = *(const u32*)(sa_hi + e0 + 16);
        ah[3] = *(const u32*)(sa_hi + e1 + 16);
        al[0] = *(const u32*)(sa_lo + e0);
        al[1] = *(const u32*)(sa_lo + e1);
        al[2] = *(const u32*)(sa_lo + e0 + 16);
        al[3] = *(const u32*)(sa_lo + e1 + 16);
#pragma unroll
        for (int nt = 0; nt < NT; ++nt) {
            const int be = ((ncol0 + nt * 8 + g) * PITCH + k0 + 2 * c) * 2;
            u32 bh0 = *(const u32*)(sb_hi + be);
            u32 bh1 = *(const u32*)(sb_hi + be + 16);
            u32 bl0 = *(const u32*)(sb_lo + be);
            u32 bl1 = *(const u32*)(sb_lo + be + 16);
            mma16816(acc[nt], ah, bh0, bh1);
            mma16816(acc[nt], ah, bl0, bl1);
            mma16816(acc[nt], al, bh0, bh1);
        }
    }
}

// ---------------------------------------------------------------------------
// wprep: blocks 0-2 split/transpose Wq/Wk/Wv; block 3 resets sync state.
// ---------------------------------------------------------------------------
__global__ __launch_bounds__(256) void wprep_kernel(
    const float* __restrict__ Wq, const float* __restrict__ Wk,
    const float* __restrict__ Wv)
{
    if (blockIdx.x == 3) {
        if (threadIdx.x < NBR) { g_ctr[threadIdx.x] = 0; g_flag[threadIdx.x] = 0; }
        return;
    }
    const float* Wl[3] = {Wq, Wk, Wv};
    const float* W = Wl[blockIdx.x];
    __nv_bfloat16* hi = g_wt[blockIdx.x][0];
    __nv_bfloat16* lo = g_wt[blockIdx.x][1];
    for (int i = threadIdx.x; i < 128 * 128; i += 256) {
        int k = i >> 7, n = i & 127;
        float v = W[i];
        __nv_bfloat16 h = __float2bfloat16(v);
        __nv_bfloat16 l = __float2bfloat16(v - __bfloat162float(h));
        hi[n * PITCH + k] = h;
        lo[n * PITCH + k] = l;
    }
}

// ---------------------------------------------------------------------------
// Fused kernel: QKV + KtV partials + group fold + out. 128 rows/CTA, 512 thr.
// smem regions:
//   QA: x split   -> (fold scratch) -> q' split
//   QB: W split   -> v split -> Wq -> G split
//   KS: k split   -> q fp32 staging (pitch QP)
// ---------------------------------------------------------------------------
#define QA_HI 0
#define QA_LO 34816
#define QB_HI 69632
#define QB_LO 104448
#define KS_HI 139264
#define KS_LO 174080
#define QBIAS 208896             // 3*128 f (bq,bk,bv)
#define QKSUM 210432             // 8*128 f slots; later ksum[128]+bo[128]
#define QMISC 214528             // int flags
#define SMEM_F (QMISC + 16)

__global__ __launch_bounds__(512, 1) void fused_kernel(
    const float* __restrict__ x,
    const float* __restrict__ bq, const float* __restrict__ bk,
    const float* __restrict__ bv, const float* __restrict__ Wo,
    const float* __restrict__ bo, float* __restrict__ out)
{
    extern __shared__ char smem[];
    const u32 sb = smem_u32(smem);
    const int tid = threadIdx.x;
    const int wid = tid >> 5;
    const int lane = tid & 31;
    const int g = lane >> 2, c = lane & 3;
    const size_t row0 = (size_t)blockIdx.x * 128;
    const int br = blockIdx.x >> 4;   // group = (b,r)

    float* sbias = (float*)(smem + QBIAS);
    float* sksum = (float*)(smem + QKSUM);
    int*   smisc = (int*)(smem + QMISC);

    if (tid < 128) {
        sbias[tid]       = bq[tid];
        sbias[128 + tid] = bk[tid];
        sbias[256 + tid] = bv[tid];
    }

    // load x tile, split hi/lo bf16 into QA [row][k]
    {
        const float4* xg = reinterpret_cast<const float4*>(x + row0 * EDIM);
#pragma unroll
        for (int i = 0; i < 8; ++i) {
            int idx = tid + i * 512;
            int row = idx >> 5;
            int c4  = (idx & 31) << 2;
            float4 v = xg[idx];
            u32 h01 = pack_bf2(v.x, v.y);
            u32 h23 = pack_bf2(v.z, v.w);
            float hx = __bfloat162float(*(__nv_bfloat16*)&h01);
            float hy = __bfloat162float(((__nv_bfloat16*)&h01)[1]);
            float hz = __bfloat162float(*(__nv_bfloat16*)&h23);
            float hw = __bfloat162float(((__nv_bfloat16*)&h23)[1]);
            u32 l01 = pack_bf2(v.x - hx, v.y - hy);
            u32 l23 = pack_bf2(v.z - hz, v.w - hw);
            int off = (row * PITCH + c4) * 2;
            *(uint2*)(smem + QA_HI + off) = make_uint2(h01, h23);
            *(uint2*)(smem + QA_LO + off) = make_uint2(l01, l23);
        }
    }

    const int arow = (wid & 7) * 16;
    const int ncol0 = (wid >> 3) * 64;
    const int aw = wid & 7;

    // ---- lambda-free weight loader ----
#define LOAD_W(widx) do {                                                   \
        const uint4* gh = (const uint4*)g_wt[widx][0];                      \
        const uint4* gl = (const uint4*)g_wt[widx][1];                      \
        uint4* sh = (uint4*)(smem + QB_HI);                                 \
        uint4* sl = (uint4*)(smem + QB_LO);                                 \
        _Pragma("unroll")                                                   \
        for (int i = 0; i < 5; ++i) {                                       \
            int idx = tid + i * 512;                                        \
            if (idx < 2176) { sh[idx] = gh[idx]; sl[idx] = gl[idx]; }       \
        }                                                                   \
    } while (0)

    // ================= k projection =================
    __syncthreads();
    LOAD_W(1);
    __syncthreads();
    {
        float acc[8][4];
#pragma unroll
        for (int i = 0; i < 8; ++i)
#pragma unroll
            for (int j = 0; j < 4; ++j) acc[i][j] = 0.f;
        gemm3p<8>(smem + QA_HI, smem + QA_LO, smem + QB_HI, smem + QB_LO,
                  arow, ncol0, lane, acc);
        const float* bias = sbias + 128;
#pragma unroll
        for (int nt = 0; nt < 8; ++nt) {
            int col = ncol0 + nt * 8 + 2 * c;
            float2 bb = *(const float2*)(bias + col);
            float k0x = elu1(acc[nt][0] + bb.x), k0y = elu1(acc[nt][1] + bb.y);
            float k1x = elu1(acc[nt][2] + bb.x), k1y = elu1(acc[nt][3] + bb.y);
            u32 h0 = pack_bf2(k0x, k0y);
            u32 h1 = pack_bf2(k1x, k1y);
            float h0x = __bfloat162float(*(__nv_bfloat16*)&h0);
            float h0y = __bfloat162float(((__nv_bfloat16*)&h0)[1]);
            float h1x = __bfloat162float(*(__nv_bfloat16*)&h1);
            float h1y = __bfloat162float(((__nv_bfloat16*)&h1)[1]);
            u32 l0 = pack_bf2(k0x - h0x, k0y - h0y);
            u32 l1 = pack_bf2(k1x - h1x, k1y - h1y);
            int o0 = ((arow + g) * PITCH + col) * 2;
            int o1 = ((arow + g + 8) * PITCH + col) * 2;
            *(u32*)(smem + KS_HI + o0) = h0;
            *(u32*)(smem + KS_LO + o0) = l0;
            *(u32*)(smem + KS_HI + o1) = h1;
            *(u32*)(smem + KS_LO + o1) = l1;
            float s0 = k0x + k1x;
            float s1 = k0y + k1y;
            s0 += __shfl_xor_sync(0xffffffffu, s0, 16);
            s0 += __shfl_xor_sync(0xffffffffu, s0, 8);
            s0 += __shfl_xor_sync(0xffffffffu, s0, 4);
            s1 += __shfl_xor_sync(0xffffffffu, s1, 16);
            s1 += __shfl_xor_sync(0xffffffffu, s1, 8);
            s1 += __shfl_xor_sync(0xffffffffu, s1, 4);
            if (lane < 4) {
                sksum[aw * 128 + col]     = s0;
                sksum[aw * 128 + col + 1] = s1;
            }
        }
    }

    // ================= v projection =================
    __syncthreads();
    LOAD_W(2);
    __syncthreads();
    {
        float acc[8][4];
#pragma unroll
        for (int i = 0; i < 8; ++i)
#pragma unroll
            for (int j = 0; j < 4; ++j) acc[i][j] = 0.f;
        gemm3p<8>(smem + QA_HI, smem + QA_LO, smem + QB_HI, smem + QB_LO,
                  arow, ncol0, lane, acc);
        const float* bias = sbias + 256;
#pragma unroll
        for (int nt = 0; nt < 8; ++nt) {
            int col = ncol0 + nt * 8 + 2 * c;
            float2 bb = *(const float2*)(bias + col);
            acc[nt][0] += bb.x; acc[nt][1] += bb.y;
            acc[nt][2] += bb.x; acc[nt][3] += bb.y;
        }
        __syncthreads();   // all reads of Wv done -> overwrite QB with v split
#pragma unroll
        for (int nt = 0; nt < 8; ++nt) {
            int col = ncol0 + nt * 8 + 2 * c;
            u32 h0 = pack_bf2(acc[nt][0], acc[nt][1]);
            u32 h1 = pack_bf2(acc[nt][2], acc[nt][3]);
            float h0x = __bfloat162float(*(__nv_bfloat16*)&h0);
            float h0y = __bfloat162float(((__nv_bfloat16*)&h0)[1]);
            float h1x = __bfloat162float(*(__nv_bfloat16*)&h1);
            float h1y = __bfloat162float(((__nv_bfloat16*)&h1)[1]);
            u32 l0 = pack_bf2(acc[nt][0] - h0x, acc[nt][1] - h0y);
            u32 l1 = pack_bf2(acc[nt][2] - h1x, acc[nt][3] - h1y);
            int o0 = ((arow + g) * PITCH + col) * 2;
            int o1 = ((arow + g + 8) * PITCH + col) * 2;
            *(u32*)(smem + QB_HI + o0) = h0;
            *(u32*)(smem + QB_LO + o0) = l0;
            *(u32*)(smem + QB_HI + o1) = h1;
            *(u32*)(smem + QB_LO + o1) = l1;
        }
    }
    __syncthreads();   // v split + sksum ready

    // ksum partial -> g_part
    if (tid < 128) {
        float s = 0.f;
#pragma unroll
        for (int i = 0; i < 8; ++i) s += sksum[i * 128 + tid];
        g_part[(size_t)blockIdx.x * PART_STRIDE + 4096 + tid] = s;
    }

    // ================= KtV partial phase =================
    {
        const int h  = wid & 3;
        const int mt = (wid >> 2) & 1;
        const int np = wid >> 3;
        const int d0 = h * 32 + mt * 16;
        const int e0 = h * 32 + np * 16;

        const u32 a_roff = (u32)(((lane & 7) + ((lane & 16) ? 8 : 0)) * (PITCH * 2));
        const u32 a_coff = (u32)((d0 + ((lane & 8) ? 8 : 0)) * 2);
        const u32 b_roff = (u32)(((lane & 7) + ((lane & 8) ? 8 : 0)) * (PITCH * 2));
        const u32 b_coff = (u32)((e0 + ((lane & 16) ? 8 : 0)) * 2);
        const u32 a_hi = sb + KS_HI + a_roff + a_coff;
        const u32 a_lo = sb + KS_LO + a_roff + a_coff;
        const u32 b_hi = sb + QB_HI + b_roff + b_coff;
        const u32 b_lo = sb + QB_LO + b_roff + b_coff;

        float acc[2][4];
#pragma unroll
        for (int i = 0; i < 2; ++i)
#pragma unroll
            for (int j = 0; j < 4; ++j) acc[i][j] = 0.f;

#pragma unroll
        for (int c0 = 0; c0 < 128; c0 += 16) {
            u32 off = (u32)(c0 * (PITCH * 2));
            u32 ah[4], al[4], bh[4], bl[4];
            ldsm_x4_t(ah, a_hi + off);
            ldsm_x4_t(al, a_lo + off);
            ldsm_x4_t(bh, b_hi + off);
            ldsm_x4_t(bl, b_lo + off);
            mma16816(acc[0], ah, bh[0], bh[1]);
            mma16816(acc[0], ah, bl[0], bl[1]);
            mma16816(acc[0], al, bh[0], bh[1]);
            mma16816(acc[1], ah, bh[2], bh[3]);
            mma16816(acc[1], ah, bl[2], bl[3]);
            mma16816(acc[1], al, bh[2], bh[3]);
        }

        float* dst = g_part + (size_t)blockIdx.x * PART_STRIDE + h * 1024;
#pragma unroll
        for (int nt = 0; nt < 2; ++nt) {
            int d_lo = mt * 16 + g;
            int e_lo = np * 16 + nt * 8 + 2 * c;
            *(float2*)&dst[d_lo * 32 + e_lo]       = make_float2(acc[nt][0], acc[nt][1]);
            *(float2*)&dst[(d_lo + 8) * 32 + e_lo] = make_float2(acc[nt][2], acc[nt][3]);
        }
    }

    // ================= q projection (into smem staging) =================
    __syncthreads();   // KtV reads of KS/QB done
    LOAD_W(0);
    __syncthreads();
    {
        float acc[8][4];
#pragma unroll
        for (int i = 0; i < 8; ++i)
#pragma unroll
            for (int j = 0; j < 4; ++j) acc[i][j] = 0.f;
        gemm3p<8>(smem + QA_HI, smem + QA_LO, smem + QB_HI, smem + QB_LO,
                  arow, ncol0, lane, acc);
        float* qsf = (float*)(smem + KS_HI);   // q fp32 staging, pitch QP
        const float* bias = sbias;
#pragma unroll
        for (int nt = 0; nt < 8; ++nt) {
            int col = ncol0 + nt * 8 + 2 * c;
            float2 bb = *(const float2*)(bias + col);
            float2 r0, r1;
            r0.x = elu1(acc[nt][0] + bb.x); r0.y = elu1(acc[nt][1] + bb.y);
            r1.x = elu1(acc[nt][2] + bb.x); r1.y = elu1(acc[nt][3] + bb.y);
            *(float2*)(qsf + (arow + g) * QP + col)     = r0;
            *(float2*)(qsf + (arow + g + 8) * QP + col) = r1;
        }
    }
    __syncthreads();   // q staging + g_part stores program-ordered before atomic

    // ================= group handshake =================
    if (tid == 0) {
        int old = atom_add_acqrel(&g_ctr[br]);
        smisc[0] = (old == GSIZE - 1) ? 1 : 0;
    }
    __syncthreads();

    if (smisc[0]) {
        // -------- fold (this CTA is last arriver of its group) --------
        float* ktv_s = (float*)(smem + QA_HI);            // 4096 f
        float* ws    = (float*)(smem + QA_HI + 16384);    // 4096 f
        const float* base = g_part + (size_t)(br * GSIZE) * PART_STRIDE;

        // KtV reduce + transpose into ktv_s[h*1024 + e*32 + d]
#pragma unroll
        for (int jj = 0; jj < 2; ++jj) {
            int f = tid + jj * 512;          // float4 index, 0..1023
            int h = f >> 8;
            int rem = f & 255;
            int d = rem >> 3;
            int e4 = (rem & 7) * 4;
            float4 v = make_float4(0.f, 0.f, 0.f, 0.f);
#pragma unroll 4
            for (int i = 0; i < GSIZE; ++i) {
                float4 p = *(const float4*)(base + (size_t)i * PART_STRIDE +
                                            h * 1024 + d * 32 + e4);
                v.x += p.x; v.y += p.y; v.z += p.z; v.w += p.w;
            }
            ktv_s[h * 1024 + (e4 + 0) * 32 + d] = v.x;
            ktv_s[h * 1024 + (e4 + 1) * 32 + d] = v.y;
            ktv_s[h * 1024 + (e4 + 2) * 32 + d] = v.z;
            ktv_s[h * 1024 + (e4 + 3) * 32 + d] = v.w;
        }
        // ksum reduce
        if (tid < 128) {
            float s = 0.f;
#pragma unroll 4
            for (int i = 0; i < GSIZE; ++i)
                s += base[(size_t)i * PART_STRIDE + 4096 + tid];
            g_ksum[(size_t)br * 128 + tid] = s;
        }

        // G fold per head
        for (int h = 0; h < 4; ++h) {
            __syncthreads();
            {
                const float4* wg = reinterpret_cast<const float4*>(Wo + h * 4096);
                float4* wsv = reinterpret_cast<float4*>(ws);
                wsv[tid]       = wg[tid];
                wsv[tid + 512] = wg[tid + 512];
            }
            __syncthreads();
            {
                const int n  = tid >> 2;
                const int d0 = (tid & 3) * 8;
                float acc[8];
#pragma unroll
                for (int j = 0; j < 8; ++j) acc[j] = 0.f;
#pragma unroll 4
                for (int dp = 0; dp < 32; ++dp) {
                    float w = ws[dp * 128 + n];
                    const float4* kp = (const float4*)(ktv_s + h * 1024 + dp * 32 + d0);
                    float4 k0 = kp[0], k1 = kp[1];
                    acc[0] += w * k0.x; acc[1] += w * k0.y;
                    acc[2] += w * k0.z; acc[3] += w * k0.w;
                    acc[4] += w * k1.x; acc[5] += w * k1.y;
                    acc[6] += w * k1.z; acc[7] += w * k1.w;
                }
                __nv_bfloat16 hbuf[8], lbuf[8];
#pragma unroll
                for (int j = 0; j < 8; ++j) {
                    __nv_bfloat16 hv = __float2bfloat16(acc[j]);
                    hbuf[j] = hv;
                    lbuf[j] = __float2bfloat16(acc[j] - __bfloat162float(hv));
                }
                int eo = n * PITCH + h * 32 + d0;
                *(uint4*)&g_G[br][0][eo] = *(uint4*)hbuf;
                *(uint4*)&g_G[br][1][eo] = *(uint4*)lbuf;
            }
        }
        __syncthreads();
        if (tid == 0) st_release(&g_flag[br], 1);
    }

    // spin for group fold completion
    if (tid == 0) {
        while (ld_acquire(&g_flag[br]) == 0) __nanosleep(64);
    }
    __syncthreads();

    // ================= out phase =================
    // ksum + bo into sksum region (free)
    float* ks_s = sksum;            // 128 f
    float* bo_s = sksum + 128;      // 128 f
    if (tid < 128) ks_s[tid] = g_ksum[(size_t)br * 128 + tid];
    else if (tid < 256) bo_s[tid - 128] = bo[tid - 128];

    // load G into QB
    {
        const uint4* gh = (const uint4*)g_G[br][0];
        const uint4* gl = (const uint4*)g_G[br][1];
        uint4* sh = (uint4*)(smem + QB_HI);
        uint4* sl = (uint4*)(smem + QB_LO);
#pragma unroll
        for (int i = 0; i < 5; ++i) {
            int idx = tid + i * 512;
            if (idx < 2176) { sh[idx] = gh[idx]; sl[idx] = gl[idx]; }
        }
    }
    __syncthreads();

    // z + q' split into QA (x dead; fold scratch dead)
    {
        const int row = tid >> 2;      // 0..127
        const int h   = tid & 3;
        const float* qrow = (const float*)(smem + KS_HI) + row * QP + h * 32;
        const float* ksp  = ks_s + h * 32;
        const int rot = (row * 4) & 31;
        float qv[32];
        float dot = 0.f;
#pragma unroll
        for (int i = 0; i < 32; ++i) {
            int ii = (i + rot) & 31;
            qv[i] = qrow[ii];
            dot += qv[i] * ksp[ii];
        }
        float z = 1.f / (dot + 1e-6f);
        __nv_bfloat16* ah = (__nv_bfloat16*)(smem + QA_HI);
        __nv_bfloat16* al = (__nv_bfloat16*)(smem + QA_LO);
#pragma unroll
        for (int i = 0; i < 32; ++i) {
            int ii = (i + rot) & 31;
            float v = qv[i] * z;
            __nv_bfloat16 hv = __float2bfloat16(v);
            int eo = row * PITCH + h * 32 + ii;
            ah[eo] = hv;
            al[eo] = __float2bfloat16(v - __bfloat162float(hv));
        }
    }
    __syncthreads();

    // out = q' @ G + bo
    {
        float acc[8][4];
#pragma unroll
        for (int i = 0; i < 8; ++i)
#pragma unroll
            for (int j = 0; j < 4; ++j) acc[i][j] = 0.f;

        gemm3p<8>(smem + QA_HI, smem + QA_LO, smem + QB_HI, smem + QB_LO,
                  arow, ncol0, lane, acc);

#pragma unroll
        for (int nt = 0; nt < 8; ++nt) {
            int col = ncol0 + nt * 8 + 2 * c;
            float2 bb = *(const float2*)(bo_s + col);
            float2 r0, r1;
            r0.x = acc[nt][0] + bb.x; r0.y = acc[nt][1] + bb.y;
            r1.x = acc[nt][2] + bb.x; r1.y = acc[nt][3] + bb.y;
            size_t ra = row0 + arow + g;
            *(float2*)(out + ra * EDIM + col)       = r0;
            *(float2*)(out + (ra + 8) * EDIM + col) = r1;
        }
    }
#undef LOAD_W
}

// ---------------------------------------------------------------------------
extern "C" void kernel_launch(void* const* d_in, const int* in_sizes, int n_in,
                              void* d_out, int out_size)
{
    const float* x  = (const float*)d_in[0];
    const float* Wq = (const float*)d_in[1];
    const float* bq = (const float*)d_in[2];
    const float* Wk = (const float*)d_in[3];
    const float* bk = (const float*)d_in[4];
    const float* Wv = (const float*)d_in[5];
    const float* bv = (const float*)d_in[6];
    const float* Wo = (const float*)d_in[7];
    const float* bo = (const float*)d_in[8];
    float* out = (float*)d_out;

    cudaFuncSetAttribute(fused_kernel, cudaFuncAttributeMaxDynamicSharedMemorySize, SMEM_F);

    wprep_kernel<<<4, 256>>>(Wq, Wk, Wv);
    fused_kernel<<<NCTA, 512, SMEM_F>>>(x, bq, bk, bv, Wo, bo, out);
}

// round 8
// speedup vs baseline: 1.5116x; 1.5116x over previous
#include <cuda_runtime.h>
#include <cuda_bf16.h>
#include <cstdint>

#define BATCH 2
#define RDIM  64
#define CDIM  2048
#define EDIM  128
#define HEADS 4
#define DHEAD 32
#define NROWS (BATCH*RDIM*CDIM)      // 262144
#define NBR   (BATCH*RDIM)           // 128
#define NCTA  (NROWS/128)            // 2048 qkv CTAs
#define PART_STRIDE 4224             // 4*32*32 ktv + 128 ksum floats per CTA

#define PITCH 136                     // bf16 elements per row

typedef unsigned int u32;

// Scratch (device globals: allocation-free rule)
__device__ float g_q[(size_t)NROWS * EDIM];
__device__ float g_ksum[(size_t)NBR * HEADS * DHEAD];
__device__ __align__(16) float g_part[(size_t)NCTA * PART_STRIDE];
__device__ __align__(16) __nv_bfloat16 g_G[NBR][2][128 * PITCH];
__device__ __align__(16) __nv_bfloat16 g_wt[3][2][128 * PITCH];

__device__ __forceinline__ float elu1(float x) {
    return x > 0.f ? x + 1.f : expf(x);
}

__device__ __forceinline__ void mma16816(float* d, const u32* a, u32 b0, u32 b1) {
    asm volatile(
        "mma.sync.aligned.m16n8k16.row.col.f32.bf16.bf16.f32 "
        "{%0,%1,%2,%3}, {%4,%5,%6,%7}, {%8,%9}, {%0,%1,%2,%3};"
        : "+f"(d[0]), "+f"(d[1]), "+f"(d[2]), "+f"(d[3])
        : "r"(a[0]), "r"(a[1]), "r"(a[2]), "r"(a[3]), "r"(b0), "r"(b1));
}

__device__ __forceinline__ void ldsm_x4(u32* r, u32 addr) {
    asm volatile("ldmatrix.sync.aligned.m8n8.x4.shared.b16 {%0,%1,%2,%3}, [%4];"
        : "=r"(r[0]), "=r"(r[1]), "=r"(r[2]), "=r"(r[3]) : "r"(addr));
}

__device__ __forceinline__ void ldsm_x4_t(u32* r, u32 addr) {
    asm volatile("ldmatrix.sync.aligned.m8n8.x4.trans.shared.b16 {%0,%1,%2,%3}, [%4];"
        : "=r"(r[0]), "=r"(r[1]), "=r"(r[2]), "=r"(r[3]) : "r"(addr));
}

__device__ __forceinline__ uint32_t smem_u32(const void* p) {
    uint32_t a;
    asm("{ .reg .u64 t; cvta.to.shared.u64 t, %1; cvt.u32.u64 %0, t; }" : "=r"(a) : "l"(p));
    return a;
}

__device__ __forceinline__ u32 pack_bf2(float x, float y) {
    __nv_bfloat162 p = __floats2bfloat162_rn(x, y);
    return *(u32*)&p;
}

// ---------------------------------------------------------------------------
// 3-pass split GEMM, ldmatrix fragment loads. K=128, 8 n-tiles (64 cols).
// aHi/aLo: per-lane A ldmatrix base (rows arow..arow+15, k=0 slice)
// bHi/bLo: per-lane B ldmatrix base (rows ncol0..ncol0+15, k=0 slice)
// A lane addr: (arow + (lane&15))*PITCH + ((lane&16)?8:0)    [elements]
// B lane addr: (ncol0 + (lane&7) + ((lane&16)?8:0))*PITCH + ((lane&8)?8:0)
// ---------------------------------------------------------------------------
__device__ __forceinline__ void gemm3p_ldsm(
    u32 aHi, u32 aLo, u32 bHi, u32 bLo, float acc[8][4])
{
#pragma unroll
    for (int k0 = 0; k0 < 128; k0 += 16) {
        const u32 koff = (u32)(k0 * 2);
        u32 ah[4], al[4];
        ldsm_x4(ah, aHi + koff);
        ldsm_x4(al, aLo + koff);
#pragma unroll
        for (int np = 0; np < 4; ++np) {
            const u32 boff = koff + (u32)(np * 16 * PITCH * 2);
            u32 bh[4], bl[4];
            ldsm_x4(bh, bHi + boff);
            ldsm_x4(bl, bLo + boff);
            mma16816(acc[2 * np],     ah, bh[0], bh[1]);
            mma16816(acc[2 * np],     ah, bl[0], bl[1]);
            mma16816(acc[2 * np],     al, bh[0], bh[1]);
            mma16816(acc[2 * np + 1], ah, bh[2], bh[3]);
            mma16816(acc[2 * np + 1], ah, bl[2], bl[3]);
            mma16816(acc[2 * np + 1], al, bh[2], bh[3]);
        }
    }
}

__device__ __forceinline__ u32 a_base(u32 sb, int region, int arow, int lane) {
    return sb + (u32)region +
        (u32)(((arow + (lane & 15)) * PITCH + ((lane & 16) ? 8 : 0)) * 2);
}
__device__ __forceinline__ u32 b_base(u32 sb, int region, int ncol0, int lane) {
    return sb + (u32)region +
        (u32)(((ncol0 + (lane & 7) + ((lane & 16) ? 8 : 0)) * PITCH +
               ((lane & 8) ? 8 : 0)) * 2);
}

// ---------------------------------------------------------------------------
// wprep: W[k][n] fp32 -> Wt[n][k] bf16 hi/lo. grid=3 (Wq, Wk, Wv).
// ---------------------------------------------------------------------------
__global__ __launch_bounds__(256) void wprep_kernel(
    const float* __restrict__ Wq, const float* __restrict__ Wk,
    const float* __restrict__ Wv)
{
    const float* Wl[3] = {Wq, Wk, Wv};
    const float* W = Wl[blockIdx.x];
    __nv_bfloat16* hi = g_wt[blockIdx.x][0];
    __nv_bfloat16* lo = g_wt[blockIdx.x][1];
    for (int i = threadIdx.x; i < 128 * 128; i += 256) {
        int k = i >> 7, n = i & 127;
        float v = W[i];
        __nv_bfloat16 h = __float2bfloat16(v);
        __nv_bfloat16 l = __float2bfloat16(v - __bfloat162float(h));
        hi[n * PITCH + k] = h;
        lo[n * PITCH + k] = l;
    }
}

// ---------------------------------------------------------------------------
// QKV + fused per-CTA KtV partial. 128-row tiles, 512 threads.
// ---------------------------------------------------------------------------
#define QA_HI 0
#define QA_LO 34816
#define QB_HI 69632
#define QB_LO 104448
#define KS_HI 139264
#define KS_LO 174080
#define QBIAS 208896
#define QKSUM 210432            // float[8][128]
#define SMEM_QKV (QKSUM + 8 * 128 * 4)

__global__ __launch_bounds__(512, 1) void qkv_kernel(
    const float* __restrict__ x,
    const float* __restrict__ bq, const float* __restrict__ bk,
    const float* __restrict__ bv)
{
    extern __shared__ char smem[];
    const u32 sb = smem_u32(smem);
    const int tid = threadIdx.x;
    const int wid = tid >> 5;
    const int lane = tid & 31;
    const int g = lane >> 2, c = lane & 3;
    const size_t row0 = (size_t)blockIdx.x * 128;

    float* sbias = (float*)(smem + QBIAS);
    float* sksum = (float*)(smem + QKSUM);
    if (tid < 128) {
        sbias[tid]       = bq[tid];
        sbias[128 + tid] = bk[tid];
        sbias[256 + tid] = bv[tid];
    }

    // load x tile, split hi/lo bf16 into [row][k] layout
    {
        const float4* xg = reinterpret_cast<const float4*>(x + row0 * EDIM);
#pragma unroll
        for (int i = 0; i < 8; ++i) {
            int idx = tid + i * 512;
            int row = idx >> 5;
            int c4  = (idx & 31) << 2;
            float4 v = xg[idx];
            u32 h01 = pack_bf2(v.x, v.y);
            u32 h23 = pack_bf2(v.z, v.w);
            float hx = __bfloat162float(*(__nv_bfloat16*)&h01);
            float hy = __bfloat162float(((__nv_bfloat16*)&h01)[1]);
            float hz = __bfloat162float(*(__nv_bfloat16*)&h23);
            float hw = __bfloat162float(((__nv_bfloat16*)&h23)[1]);
            u32 l01 = pack_bf2(v.x - hx, v.y - hy);
            u32 l23 = pack_bf2(v.z - hz, v.w - hw);
            int off = (row * PITCH + c4) * 2;
            *(uint2*)(smem + QA_HI + off) = make_uint2(h01, h23);
            *(uint2*)(smem + QA_LO + off) = make_uint2(l01, l23);
        }
    }

    const int arow = (wid & 7) * 16;
    const int ncol0 = (wid >> 3) * 64;
    const int aw = wid & 7;

    const u32 aHi = a_base(sb, QA_HI, arow, lane);
    const u32 aLo = a_base(sb, QA_LO, arow, lane);
    const u32 bHi = b_base(sb, QB_HI, ncol0, lane);
    const u32 bLo = b_base(sb, QB_LO, ncol0, lane);

    for (int w = 0; w < 3; ++w) {
        __syncthreads();
        {
            const uint4* gh = (const uint4*)g_wt[w][0];
            const uint4* gl = (const uint4*)g_wt[w][1];
            uint4* sh = (uint4*)(smem + QB_HI);
            uint4* sl = (uint4*)(smem + QB_LO);
#pragma unroll
            for (int i = 0; i < 5; ++i) {
                int idx = tid + i * 512;
                if (idx < 2176) { sh[idx] = gh[idx]; sl[idx] = gl[idx]; }
            }
        }
        __syncthreads();

        float acc[8][4];
#pragma unroll
        for (int i = 0; i < 8; ++i)
#pragma unroll
            for (int j = 0; j < 4; ++j) acc[i][j] = 0.f;

        gemm3p_ldsm(aHi, aLo, bHi, bLo, acc);

        const float* bias = sbias + w * 128;

        if (w == 0) {
#pragma unroll
            for (int nt = 0; nt < 8; ++nt) {
                int col = ncol0 + nt * 8 + 2 * c;
                float2 bb = *(const float2*)(bias + col);
                float2 r0, r1;
                r0.x = elu1(acc[nt][0] + bb.x); r0.y = elu1(acc[nt][1] + bb.y);
                r1.x = elu1(acc[nt][2] + bb.x); r1.y = elu1(acc[nt][3] + bb.y);
                size_t ra = row0 + arow + g;
                *(float2*)(g_q + ra * EDIM + col)       = r0;
                *(float2*)(g_q + (ra + 8) * EDIM + col) = r1;
            }
        } else if (w == 1) {
#pragma unroll
            for (int nt = 0; nt < 8; ++nt) {
                int col = ncol0 + nt * 8 + 2 * c;
                float2 bb = *(const float2*)(bias + col);
                float k0x = elu1(acc[nt][0] + bb.x), k0y = elu1(acc[nt][1] + bb.y);
                float k1x = elu1(acc[nt][2] + bb.x), k1y = elu1(acc[nt][3] + bb.y);
                u32 h0 = pack_bf2(k0x, k0y);
                u32 h1 = pack_bf2(k1x, k1y);
                float h0x = __bfloat162float(*(__nv_bfloat16*)&h0);
                float h0y = __bfloat162float(((__nv_bfloat16*)&h0)[1]);
                float h1x = __bfloat162float(*(__nv_bfloat16*)&h1);
                float h1y = __bfloat162float(((__nv_bfloat16*)&h1)[1]);
                u32 l0 = pack_bf2(k0x - h0x, k0y - h0y);
                u32 l1 = pack_bf2(k1x - h1x, k1y - h1y);
                int o0 = ((arow + g) * PITCH + col) * 2;
                int o1 = ((arow + g + 8) * PITCH + col) * 2;
                *(u32*)(smem + KS_HI + o0) = h0;
                *(u32*)(smem + KS_LO + o0) = l0;
                *(u32*)(smem + KS_HI + o1) = h1;
                *(u32*)(smem + KS_LO + o1) = l1;
                float s0 = k0x + k1x;
                float s1 = k0y + k1y;
                s0 += __shfl_xor_sync(0xffffffffu, s0, 16);
                s0 += __shfl_xor_sync(0xffffffffu, s0, 8);
                s0 += __shfl_xor_sync(0xffffffffu, s0, 4);
                s1 += __shfl_xor_sync(0xffffffffu, s1, 16);
                s1 += __shfl_xor_sync(0xffffffffu, s1, 8);
                s1 += __shfl_xor_sync(0xffffffffu, s1, 4);
                if (lane < 4) {
                    sksum[aw * 128 + col]     = s0;
                    sksum[aw * 128 + col + 1] = s1;
                }
            }
        } else {
#pragma unroll
            for (int nt = 0; nt < 8; ++nt) {
                int col = ncol0 + nt * 8 + 2 * c;
                float2 bb = *(const float2*)(bias + col);
                acc[nt][0] += bb.x; acc[nt][1] += bb.y;
                acc[nt][2] += bb.x; acc[nt][3] += bb.y;
            }
            __syncthreads();   // everyone done reading QB (Wv)
#pragma unroll
            for (int nt = 0; nt < 8; ++nt) {
                int col = ncol0 + nt * 8 + 2 * c;
                u32 h0 = pack_bf2(acc[nt][0], acc[nt][1]);
                u32 h1 = pack_bf2(acc[nt][2], acc[nt][3]);
                float h0x = __bfloat162float(*(__nv_bfloat16*)&h0);
                float h0y = __bfloat162float(((__nv_bfloat16*)&h0)[1]);
                float h1x = __bfloat162float(*(__nv_bfloat16*)&h1);
                float h1y = __bfloat162float(((__nv_bfloat16*)&h1)[1]);
                u32 l0 = pack_bf2(acc[nt][0] - h0x, acc[nt][1] - h0y);
                u32 l1 = pack_bf2(acc[nt][2] - h1x, acc[nt][3] - h1y);
                int o0 = ((arow + g) * PITCH + col) * 2;
                int o1 = ((arow + g + 8) * PITCH + col) * 2;
                *(u32*)(smem + QB_HI + o0) = h0;
                *(u32*)(smem + QB_LO + o0) = l0;
                *(u32*)(smem + QB_HI + o1) = h1;
                *(u32*)(smem + QB_LO + o1) = l1;
            }
        }
    }

    __syncthreads();   // v-split writes + sksum complete

    if (tid < 128) {
        float s = 0.f;
#pragma unroll
        for (int i = 0; i < 8; ++i) s += sksum[i * 128 + tid];
        g_part[(size_t)blockIdx.x * PART_STRIDE + 4096 + tid] = s;
    }

    // ---- KtV partial phase ----
    {
        const int h  = wid & 3;
        const int mt = (wid >> 2) & 1;
        const int np = wid >> 3;
        const int d0 = h * 32 + mt * 16;
        const int e0 = h * 32 + np * 16;

        const u32 a_roff = (u32)(((lane & 7) + ((lane & 16) ? 8 : 0)) * (PITCH * 2));
        const u32 a_coff = (u32)((d0 + ((lane & 8) ? 8 : 0)) * 2);
        const u32 b_roff = (u32)(((lane & 7) + ((lane & 8) ? 8 : 0)) * (PITCH * 2));
        const u32 b_coff = (u32)((e0 + ((lane & 16) ? 8 : 0)) * 2);
        const u32 a_hi = sb + KS_HI + a_roff + a_coff;
        const u32 a_lo = sb + KS_LO + a_roff + a_coff;
        const u32 b_hi = sb + QB_HI + b_roff + b_coff;
        const u32 b_lo = sb + QB_LO + b_roff + b_coff;

        float acc[2][4];
#pragma unroll
        for (int i = 0; i < 2; ++i)
#pragma unroll
            for (int j = 0; j < 4; ++j) acc[i][j] = 0.f;

#pragma unroll
        for (int c0 = 0; c0 < 128; c0 += 16) {
            u32 off = (u32)(c0 * (PITCH * 2));
            u32 ah[4], al[4], bh[4], bl[4];
            ldsm_x4_t(ah, a_hi + off);
            ldsm_x4_t(al, a_lo + off);
            ldsm_x4_t(bh, b_hi + off);
            ldsm_x4_t(bl, b_lo + off);
            mma16816(acc[0], ah, bh[0], bh[1]);
            mma16816(acc[0], ah, bl[0], bl[1]);
            mma16816(acc[0], al, bh[0], bh[1]);
            mma16816(acc[1], ah, bh[2], bh[3]);
            mma16816(acc[1], ah, bl[2], bl[3]);
            mma16816(acc[1], al, bh[2], bh[3]);
        }

        float* dst = g_part + (size_t)blockIdx.x * PART_STRIDE + h * 1024;
#pragma unroll
        for (int nt = 0; nt < 2; ++nt) {
            int d_lo = mt * 16 + g;
            int e_lo = np * 16 + nt * 8 + 2 * c;
            *(float2*)&dst[d_lo * 32 + e_lo]       = make_float2(acc[nt][0], acc[nt][1]);
            *(float2*)&dst[(d_lo + 8) * 32 + e_lo] = make_float2(acc[nt][2], acc[nt][3]);
        }
    }
}

// ---------------------------------------------------------------------------
// fold: per (br,h): reduce 16 CTA partials -> KtV; ksum (h==0);
//       G[d][n] = sum_d' KtV[d][d']*Wo[h*32+d'][n] -> split bf16 [n][k].
// ---------------------------------------------------------------------------
__global__ __launch_bounds__(256) void fold_kernel(const float* __restrict__ Wo)
{
    __shared__ float ktv_s[1024];   // [e][d]
    __shared__ float ws[4096];      // Wo slice [32][128]

    const int tid = threadIdx.x;
    const int br  = blockIdx.x >> 2;
    const int h   = blockIdx.x & 3;
    const float* base = g_part + (size_t)br * 16 * PART_STRIDE;

    {
        float v0 = 0.f, v1 = 0.f, v2 = 0.f, v3 = 0.f;
#pragma unroll 4
        for (int i = 0; i < 16; ++i) {
            float4 p = *(const float4*)(base + (size_t)i * PART_STRIDE + h * 1024 + tid * 4);
            v0 += p.x; v1 += p.y; v2 += p.z; v3 += p.w;
        }
        int d = tid >> 3, e0 = (tid & 7) * 4;
        ktv_s[(e0 + 0) * 32 + d] = v0;
        ktv_s[(e0 + 1) * 32 + d] = v1;
        ktv_s[(e0 + 2) * 32 + d] = v2;
        ktv_s[(e0 + 3) * 32 + d] = v3;
    }

    if (h == 0 && tid < 128) {
        float s = 0.f;
#pragma unroll 4
        for (int i = 0; i < 16; ++i)
            s += base[(size_t)i * PART_STRIDE + 4096 + tid];
        g_ksum[(size_t)br * 128 + tid] = s;
    }

    {
        const float4* wg = reinterpret_cast<const float4*>(Wo + h * 4096);
#pragma unroll
        for (int i = 0; i < 4; ++i)
            reinterpret_cast<float4*>(ws)[tid + i * 256] = wg[tid + i * 256];
    }
    __syncthreads();

    {
        const int n  = tid >> 1;
        const int d0 = (tid & 1) * 16;
        float acc[16];
#pragma unroll
        for (int j = 0; j < 16; ++j) acc[j] = 0.f;
#pragma unroll 4
        for (int dp = 0; dp < 32; ++dp) {
            float w = ws[dp * 128 + n];
            const float4* kp = (const float4*)(ktv_s + dp * 32 + d0);
            float4 k0 = kp[0], k1 = kp[1], k2 = kp[2], k3 = kp[3];
            acc[0]  += w * k0.x; acc[1]  += w * k0.y; acc[2]  += w * k0.z; acc[3]  += w * k0.w;
            acc[4]  += w * k1.x; acc[5]  += w * k1.y; acc[6]  += w * k1.z; acc[7]  += w * k1.w;
            acc[8]  += w * k2.x; acc[9]  += w * k2.y; acc[10] += w * k2.z; acc[11] += w * k2.w;
            acc[12] += w * k3.x; acc[13] += w * k3.y; acc[14] += w * k3.z; acc[15] += w * k3.w;
        }
        __nv_bfloat16 hbuf[16], lbuf[16];
#pragma unroll
        for (int j = 0; j < 16; ++j) {
            __nv_bfloat16 hv = __float2bfloat16(acc[j]);
            hbuf[j] = hv;
            lbuf[j] = __float2bfloat16(acc[j] - __bfloat162float(hv));
        }
        int eo = n * PITCH + h * 32 + d0;
        uint4* dh = (uint4*)&g_G[br][0][eo];
        uint4* dl = (uint4*)&g_G[br][1][eo];
        dh[0] = ((uint4*)hbuf)[0]; dh[1] = ((uint4*)hbuf)[1];
        dl[0] = ((uint4*)lbuf)[0]; dl[1] = ((uint4*)lbuf)[1];
    }
}

// ---------------------------------------------------------------------------
// out: z = 1/(q.ksum+eps); q' = q*z; out = q' @ G + bo.
// ---------------------------------------------------------------------------
#define OA_HI 0
#define OA_LO 17408
#define OG_HI 34816
#define OG_LO 69632
#define OKS   104448
#define SMEM_OUT (OKS + 512)

__global__ __launch_bounds__(256, 2) void out_kernel(
    const float* __restrict__ bo, float* __restrict__ out)
{
    extern __shared__ char smem[];
    const u32 sb = smem_u32(smem);
    float* qs    = (float*)(smem + OG_HI);
    float* ksums = (float*)(smem + OKS);

    const int tid = threadIdx.x;
    const int bx  = blockIdx.x;
    const int br  = bx >> 5;
    const int ct  = bx & 31;
    const size_t row0 = (size_t)br * CDIM + ct * 64;

    {
        const float4* qg = reinterpret_cast<const float4*>(g_q + row0 * EDIM);
#pragma unroll
        for (int i = 0; i < 8; ++i)
            reinterpret_cast<float4*>(qs)[tid + i * 256] = qg[tid + i * 256];
        if (tid < 32)
            reinterpret_cast<float4*>(ksums)[tid] =
                reinterpret_cast<const float4*>(g_ksum + (size_t)br * 128)[tid];
    }
    __syncthreads();

    {
        const int row = tid >> 2;
        const int h   = tid & 3;
        const float* qrow = qs + row * 128 + h * 32;
        const float* ksp  = ksums + h * 32;
        const int rot = (row * 4) & 31;
        float qv[32];
        float dot = 0.f;
#pragma unroll
        for (int i = 0; i < 32; ++i) {
            int ii = (i + rot) & 31;
            qv[i] = qrow[ii];
            dot += qv[i] * ksp[ii];
        }
        float z = 1.f / (dot + 1e-6f);
        __nv_bfloat16* ah = (__nv_bfloat16*)(smem + OA_HI);
        __nv_bfloat16* al = (__nv_bfloat16*)(smem + OA_LO);
#pragma unroll
        for (int i = 0; i < 32; ++i) {
            int ii = (i + rot) & 31;
            float v = qv[i] * z;
            __nv_bfloat16 hv = __float2bfloat16(v);
            int eo = row * PITCH + h * 32 + ii;
            ah[eo] = hv;
            al[eo] = __float2bfloat16(v - __bfloat162float(hv));
        }
    }
    __syncthreads();

    {
        const uint4* gh = (const uint4*)g_G[br][0];
        const uint4* gl = (const uint4*)g_G[br][1];
        uint4* sh = (uint4*)(smem + OG_HI);
        uint4* sl = (uint4*)(smem + OG_LO);
#pragma unroll
        for (int i = 0; i < 9; ++i) {
            int idx = tid + i * 256;
            if (idx < 2176) { sh[idx] = gh[idx]; sl[idx] = gl[idx]; }
        }
    }
    __syncthreads();

    {
        const int wid = tid >> 5;
        const int lane = tid & 31;
        const int g = lane >> 2, c = lane & 3;
        const int arow = (wid & 3) * 16;
        const int ncol0 = (wid >> 2) * 64;

        float acc[8][4];
#pragma unroll
        for (int i = 0; i < 8; ++i)
#pragma unroll
            for (int j = 0; j < 4; ++j) acc[i][j] = 0.f;

        gemm3p_ldsm(a_base(sb, OA_HI, arow, lane), a_base(sb, OA_LO, arow, lane),
                    b_base(sb, OG_HI, ncol0, lane), b_base(sb, OG_LO, ncol0, lane),
                    acc);

#pragma unroll
        for (int nt = 0; nt < 8; ++nt) {
            int col = ncol0 + nt * 8 + 2 * c;
            float2 bb = *(const float2*)(bo + col);
            float2 r0, r1;
            r0.x = acc[nt][0] + bb.x; r0.y = acc[nt][1] + bb.y;
            r1.x = acc[nt][2] + bb.x; r1.y = acc[nt][3] + bb.y;
            size_t ra = row0 + arow + g;
            *(float2*)(out + ra * EDIM + col)       = r0;
            *(float2*)(out + (ra + 8) * EDIM + col) = r1;
        }
    }
}

// ---------------------------------------------------------------------------
extern "C" void kernel_launch(void* const* d_in, const int* in_sizes, int n_in,
                              void* d_out, int out_size)
{
    const float* x  = (const float*)d_in[0];
    const float* Wq = (const float*)d_in[1];
    const float* bq = (const float*)d_in[2];
    const float* Wk = (const float*)d_in[3];
    const float* bk = (const float*)d_in[4];
    const float* Wv = (const float*)d_in[5];
    const float* bv = (const float*)d_in[6];
    const float* Wo = (const float*)d_in[7];
    const float* bo = (const float*)d_in[8];
    float* out = (float*)d_out;

    cudaFuncSetAttribute(qkv_kernel, cudaFuncAttributeMaxDynamicSharedMemorySize, SMEM_QKV);
    cudaFuncSetAttribute(out_kernel, cudaFuncAttributeMaxDynamicSharedMemorySize, SMEM_OUT);

    wprep_kernel<<<3, 256>>>(Wq, Wk, Wv);
    qkv_kernel<<<NCTA, 512, SMEM_QKV>>>(x, bq, bk, bv);
    fold_kernel<<<NBR * HEADS, 256>>>(Wo);
    out_kernel<<<NROWS / 64, 256, SMEM_OUT>>>(bo, out);
}

// round 9
// speedup vs baseline: 1.5707x; 1.0391x over previous
#include <cuda_runtime.h>
#include <cuda_bf16.h>
#include <cstdint>

#define BATCH 2
#define RDIM  64
#define CDIM  2048
#define EDIM  128
#define HEADS 4
#define DHEAD 32
#define NROWS (BATCH*RDIM*CDIM)      // 262144
#define NBR   (BATCH*RDIM)           // 128
#define NCTA  (NROWS/128)            // 2048
#define PART_STRIDE 4224             // 4*32*32 ktv + 128 ksum floats per CTA

#define PITCH 136                     // bf16 elements per row

typedef unsigned int u32;

// Scratch (device globals)
__device__ float g_ksum[(size_t)NBR * HEADS * DHEAD];
__device__ __align__(16) float g_part[(size_t)NCTA * PART_STRIDE];
__device__ __align__(16) __nv_bfloat16 g_G[NBR][2][128 * PITCH];
__device__ __align__(16) __nv_bfloat16 g_wt[3][2][128 * PITCH];

__device__ __forceinline__ float elu1(float x) {
    return x > 0.f ? x + 1.f : expf(x);
}

__device__ __forceinline__ void mma16816(float* d, const u32* a, u32 b0, u32 b1) {
    asm volatile(
        "mma.sync.aligned.m16n8k16.row.col.f32.bf16.bf16.f32 "
        "{%0,%1,%2,%3}, {%4,%5,%6,%7}, {%8,%9}, {%0,%1,%2,%3};"
        : "+f"(d[0]), "+f"(d[1]), "+f"(d[2]), "+f"(d[3])
        : "r"(a[0]), "r"(a[1]), "r"(a[2]), "r"(a[3]), "r"(b0), "r"(b1));
}

__device__ __forceinline__ void ldsm_x4(u32* r, u32 addr) {
    asm volatile("ldmatrix.sync.aligned.m8n8.x4.shared.b16 {%0,%1,%2,%3}, [%4];"
        : "=r"(r[0]), "=r"(r[1]), "=r"(r[2]), "=r"(r[3]) : "r"(addr));
}

__device__ __forceinline__ void ldsm_x4_t(u32* r, u32 addr) {
    asm volatile("ldmatrix.sync.aligned.m8n8.x4.trans.shared.b16 {%0,%1,%2,%3}, [%4];"
        : "=r"(r[0]), "=r"(r[1]), "=r"(r[2]), "=r"(r[3]) : "r"(addr));
}

__device__ __forceinline__ uint32_t smem_u32(const void* p) {
    uint32_t a;
    asm("{ .reg .u64 t; cvta.to.shared.u64 t, %1; cvt.u32.u64 %0, t; }" : "=r"(a) : "l"(p));
    return a;
}

__device__ __forceinline__ u32 pack_bf2(float x, float y) {
    __nv_bfloat162 p = __floats2bfloat162_rn(x, y);
    return *(u32*)&p;
}
__device__ __forceinline__ float bf_lo(u32 u) {
    return __bfloat162float(*(__nv_bfloat16*)&u);
}
__device__ __forceinline__ float bf_hi(u32 u) {
    return __bfloat162float(((__nv_bfloat16*)&u)[1]);
}

// 3-pass split GEMM, ldmatrix fragment loads. K=128, 8 n-tiles.
__device__ __forceinline__ void gemm3p_ldsm(
    u32 aHi, u32 aLo, u32 bHi, u32 bLo, float acc[8][4])
{
#pragma unroll
    for (int k0 = 0; k0 < 128; k0 += 16) {
        const u32 koff = (u32)(k0 * 2);
        u32 ah[4], al[4];
        ldsm_x4(ah, aHi + koff);
        ldsm_x4(al, aLo + koff);
#pragma unroll
        for (int np = 0; np < 4; ++np) {
            const u32 boff = koff + (u32)(np * 16 * PITCH * 2);
            u32 bh[4], bl[4];
            ldsm_x4(bh, bHi + boff);
            ldsm_x4(bl, bLo + boff);
            mma16816(acc[2 * np],     ah, bh[0], bh[1]);
            mma16816(acc[2 * np],     ah, bl[0], bl[1]);
            mma16816(acc[2 * np],     al, bh[0], bh[1]);
            mma16816(acc[2 * np + 1], ah, bh[2], bh[3]);
            mma16816(acc[2 * np + 1], ah, bl[2], bl[3]);
            mma16816(acc[2 * np + 1], al, bh[2], bh[3]);
        }
    }
}

__device__ __forceinline__ u32 a_base(u32 sb, int region, int arow, int lane) {
    return sb + (u32)region +
        (u32)(((arow + (lane & 15)) * PITCH + ((lane & 16) ? 8 : 0)) * 2);
}
__device__ __forceinline__ u32 b_base(u32 sb, int region, int ncol0, int lane) {
    return sb + (u32)region +
        (u32)(((ncol0 + (lane & 7) + ((lane & 16) ? 8 : 0)) * PITCH +
               ((lane & 8) ? 8 : 0)) * 2);
}

// ---------------------------------------------------------------------------
// wprep: W[k][n] fp32 -> Wt[n][k] bf16 hi/lo. grid=3 (Wq, Wk, Wv).
// ---------------------------------------------------------------------------
__global__ __launch_bounds__(256) void wprep_kernel(
    const float* __restrict__ Wq, const float* __restrict__ Wk,
    const float* __restrict__ Wv)
{
    const float* Wl[3] = {Wq, Wk, Wv};
    const float* W = Wl[blockIdx.x];
    __nv_bfloat16* hi = g_wt[blockIdx.x][0];
    __nv_bfloat16* lo = g_wt[blockIdx.x][1];
    for (int i = threadIdx.x; i < 128 * 128; i += 256) {
        int k = i >> 7, n = i & 127;
        float v = W[i];
        __nv_bfloat16 h = __float2bfloat16(v);
        __nv_bfloat16 l = __float2bfloat16(v - __bfloat162float(h));
        hi[n * PITCH + k] = h;
        lo[n * PITCH + k] = l;
    }
}

// ---------------------------------------------------------------------------
// KV + fused per-CTA KtV partial. 128-row tiles, 512 threads. (q pass removed)
// ---------------------------------------------------------------------------
#define QA_HI 0
#define QA_LO 34816
#define QB_HI 69632
#define QB_LO 104448
#define KS_HI 139264
#define KS_LO 174080
#define QBIAS 208896
#define QKSUM 210432            // float[8][128]
#define SMEM_KV (QKSUM + 8 * 128 * 4)

__global__ __launch_bounds__(512, 1) void kv_kernel(
    const float* __restrict__ x,
    const float* __restrict__ bk, const float* __restrict__ bv)
{
    extern __shared__ char smem[];
    const u32 sb = smem_u32(smem);
    const int tid = threadIdx.x;
    const int wid = tid >> 5;
    const int lane = tid & 31;
    const int g = lane >> 2, c = lane & 3;
    const size_t row0 = (size_t)blockIdx.x * 128;

    float* sbias = (float*)(smem + QBIAS);
    float* sksum = (float*)(smem + QKSUM);
    if (tid < 128) {
        sbias[tid]       = bk[tid];
        sbias[128 + tid] = bv[tid];
    }

    // load x tile, split hi/lo bf16 into [row][k] layout
    {
        const float4* xg = reinterpret_cast<const float4*>(x + row0 * EDIM);
#pragma unroll
        for (int i = 0; i < 8; ++i) {
            int idx = tid + i * 512;
            int row = idx >> 5;
            int c4  = (idx & 31) << 2;
            float4 v = xg[idx];
            u32 h01 = pack_bf2(v.x, v.y);
            u32 h23 = pack_bf2(v.z, v.w);
            u32 l01 = pack_bf2(v.x - bf_lo(h01), v.y - bf_hi(h01));
            u32 l23 = pack_bf2(v.z - bf_lo(h23), v.w - bf_hi(h23));
            int off = (row * PITCH + c4) * 2;
            *(uint2*)(smem + QA_HI + off) = make_uint2(h01, h23);
            *(uint2*)(smem + QA_LO + off) = make_uint2(l01, l23);
        }
    }

    const int arow = (wid & 7) * 16;
    const int ncol0 = (wid >> 3) * 64;
    const int aw = wid & 7;

    const u32 aHi = a_base(sb, QA_HI, arow, lane);
    const u32 aLo = a_base(sb, QA_LO, arow, lane);
    const u32 bHi = b_base(sb, QB_HI, ncol0, lane);
    const u32 bLo = b_base(sb, QB_LO, ncol0, lane);

    for (int w = 1; w < 3; ++w) {
        __syncthreads();
        {
            const uint4* gh = (const uint4*)g_wt[w][0];
            const uint4* gl = (const uint4*)g_wt[w][1];
            uint4* sh = (uint4*)(smem + QB_HI);
            uint4* sl = (uint4*)(smem + QB_LO);
#pragma unroll
            for (int i = 0; i < 5; ++i) {
                int idx = tid + i * 512;
                if (idx < 2176) { sh[idx] = gh[idx]; sl[idx] = gl[idx]; }
            }
        }
        __syncthreads();

        float acc[8][4];
#pragma unroll
        for (int i = 0; i < 8; ++i)
#pragma unroll
            for (int j = 0; j < 4; ++j) acc[i][j] = 0.f;

        gemm3p_ldsm(aHi, aLo, bHi, bLo, acc);

        if (w == 1) {
            const float* bias = sbias;
#pragma unroll
            for (int nt = 0; nt < 8; ++nt) {
                int col = ncol0 + nt * 8 + 2 * c;
                float2 bb = *(const float2*)(bias + col);
                float k0x = elu1(acc[nt][0] + bb.x), k0y = elu1(acc[nt][1] + bb.y);
                float k1x = elu1(acc[nt][2] + bb.x), k1y = elu1(acc[nt][3] + bb.y);
                u32 h0 = pack_bf2(k0x, k0y);
                u32 h1 = pack_bf2(k1x, k1y);
                u32 l0 = pack_bf2(k0x - bf_lo(h0), k0y - bf_hi(h0));
                u32 l1 = pack_bf2(k1x - bf_lo(h1), k1y - bf_hi(h1));
                int o0 = ((arow + g) * PITCH + col) * 2;
                int o1 = ((arow + g + 8) * PITCH + col) * 2;
                *(u32*)(smem + KS_HI + o0) = h0;
                *(u32*)(smem + KS_LO + o0) = l0;
                *(u32*)(smem + KS_HI + o1) = h1;
                *(u32*)(smem + KS_LO + o1) = l1;
                float s0 = k0x + k1x;
                float s1 = k0y + k1y;
                s0 += __shfl_xor_sync(0xffffffffu, s0, 16);
                s0 += __shfl_xor_sync(0xffffffffu, s0, 8);
                s0 += __shfl_xor_sync(0xffffffffu, s0, 4);
                s1 += __shfl_xor_sync(0xffffffffu, s1, 16);
                s1 += __shfl_xor_sync(0xffffffffu, s1, 8);
                s1 += __shfl_xor_sync(0xffffffffu, s1, 4);
                if (lane < 4) {
                    sksum[aw * 128 + col]     = s0;
                    sksum[aw * 128 + col + 1] = s1;
                }
            }
        } else {
            const float* bias = sbias + 128;
#pragma unroll
            for (int nt = 0; nt < 8; ++nt) {
                int col = ncol0 + nt * 8 + 2 * c;
                float2 bb = *(const float2*)(bias + col);
                acc[nt][0] += bb.x; acc[nt][1] += bb.y;
                acc[nt][2] += bb.x; acc[nt][3] += bb.y;
            }
            __syncthreads();   // everyone done reading QB (Wv)
#pragma unroll
            for (int nt = 0; nt < 8; ++nt) {
                int col = ncol0 + nt * 8 + 2 * c;
                u32 h0 = pack_bf2(acc[nt][0], acc[nt][1]);
                u32 h1 = pack_bf2(acc[nt][2], acc[nt][3]);
                u32 l0 = pack_bf2(acc[nt][0] - bf_lo(h0), acc[nt][1] - bf_hi(h0));
                u32 l1 = pack_bf2(acc[nt][2] - bf_lo(h1), acc[nt][3] - bf_hi(h1));
                int o0 = ((arow + g) * PITCH + col) * 2;
                int o1 = ((arow + g + 8) * PITCH + col) * 2;
                *(u32*)(smem + QB_HI + o0) = h0;
                *(u32*)(smem + QB_LO + o0) = l0;
                *(u32*)(smem + QB_HI + o1) = h1;
                *(u32*)(smem + QB_LO + o1) = l1;
            }
        }
    }

    __syncthreads();   // v-split writes + sksum complete

    if (tid < 128) {
        float s = 0.f;
#pragma unroll
        for (int i = 0; i < 8; ++i) s += sksum[i * 128 + tid];
        g_part[(size_t)blockIdx.x * PART_STRIDE + 4096 + tid] = s;
    }

    // ---- KtV partial phase ----
    {
        const int h  = wid & 3;
        const int mt = (wid >> 2) & 1;
        const int np = wid >> 3;
        const int d0 = h * 32 + mt * 16;
        const int e0 = h * 32 + np * 16;

        const u32 a_roff = (u32)(((lane & 7) + ((lane & 16) ? 8 : 0)) * (PITCH * 2));
        const u32 a_coff = (u32)((d0 + ((lane & 8) ? 8 : 0)) * 2);
        const u32 b_roff = (u32)(((lane & 7) + ((lane & 8) ? 8 : 0)) * (PITCH * 2));
        const u32 b_coff = (u32)((e0 + ((lane & 16) ? 8 : 0)) * 2);
        const u32 a_hi = sb + KS_HI + a_roff + a_coff;
        const u32 a_lo = sb + KS_LO + a_roff + a_coff;
        const u32 b_hi = sb + QB_HI + b_roff + b_coff;
        const u32 b_lo = sb + QB_LO + b_roff + b_coff;

        float acc[2][4];
#pragma unroll
        for (int i = 0; i < 2; ++i)
#pragma unroll
            for (int j = 0; j < 4; ++j) acc[i][j] = 0.f;

#pragma unroll
        for (int c0 = 0; c0 < 128; c0 += 16) {
            u32 off = (u32)(c0 * (PITCH * 2));
            u32 ah[4], al[4], bh[4], bl[4];
            ldsm_x4_t(ah, a_hi + off);
            ldsm_x4_t(al, a_lo + off);
            ldsm_x4_t(bh, b_hi + off);
            ldsm_x4_t(bl, b_lo + off);
            mma16816(acc[0], ah, bh[0], bh[1]);
            mma16816(acc[0], ah, bl[0], bl[1]);
            mma16816(acc[0], al, bh[0], bh[1]);
            mma16816(acc[1], ah, bh[2], bh[3]);
            mma16816(acc[1], ah, bl[2], bl[3]);
            mma16816(acc[1], al, bh[2], bh[3]);
        }

        float* dst = g_part + (size_t)blockIdx.x * PART_STRIDE + h * 1024;
#pragma unroll
        for (int nt = 0; nt < 2; ++nt) {
            int d_lo = mt * 16 + g;
            int e_lo = np * 16 + nt * 8 + 2 * c;
            *(float2*)&dst[d_lo * 32 + e_lo]       = make_float2(acc[nt][0], acc[nt][1]);
            *(float2*)&dst[(d_lo + 8) * 32 + e_lo] = make_float2(acc[nt][2], acc[nt][3]);
        }
    }
}

// ---------------------------------------------------------------------------
// fold: per (br,h): reduce 16 CTA partials -> KtV; ksum (h==0);
//       G[d][n] = sum_d' KtV[d][d']*Wo[h*32+d'][n] -> split bf16 [n][k].
// ---------------------------------------------------------------------------
__global__ __launch_bounds__(256) void fold_kernel(const float* __restrict__ Wo)
{
    __shared__ float ktv_s[1024];   // [e][d]
    __shared__ float ws[4096];      // Wo slice [32][128]

    const int tid = threadIdx.x;
    const int br  = blockIdx.x >> 2;
    const int h   = blockIdx.x & 3;
    const float* base = g_part + (size_t)br * 16 * PART_STRIDE;

    {
        float v0 = 0.f, v1 = 0.f, v2 = 0.f, v3 = 0.f;
#pragma unroll 4
        for (int i = 0; i < 16; ++i) {
            float4 p = *(const float4*)(base + (size_t)i * PART_STRIDE + h * 1024 + tid * 4);
            v0 += p.x; v1 += p.y; v2 += p.z; v3 += p.w;
        }
        int d = tid >> 3, e0 = (tid & 7) * 4;
        ktv_s[(e0 + 0) * 32 + d] = v0;
        ktv_s[(e0 + 1) * 32 + d] = v1;
        ktv_s[(e0 + 2) * 32 + d] = v2;
        ktv_s[(e0 + 3) * 32 + d] = v3;
    }

    if (h == 0 && tid < 128) {
        float s = 0.f;
#pragma unroll 4
        for (int i = 0; i < 16; ++i)
            s += base[(size_t)i * PART_STRIDE + 4096 + tid];
        g_ksum[(size_t)br * 128 + tid] = s;
    }

    {
        const float4* wg = reinterpret_cast<const float4*>(Wo + h * 4096);
#pragma unroll
        for (int i = 0; i < 4; ++i)
            reinterpret_cast<float4*>(ws)[tid + i * 256] = wg[tid + i * 256];
    }
    __syncthreads();

    {
        const int n  = tid >> 1;
        const int d0 = (tid & 1) * 16;
        float acc[16];
#pragma unroll
        for (int j = 0; j < 16; ++j) acc[j] = 0.f;
#pragma unroll 4
        for (int dp = 0; dp < 32; ++dp) {
            float w = ws[dp * 128 + n];
            const float4* kp = (const float4*)(ktv_s + dp * 32 + d0);
            float4 k0 = kp[0], k1 = kp[1], k2 = kp[2], k3 = kp[3];
            acc[0]  += w * k0.x; acc[1]  += w * k0.y; acc[2]  += w * k0.z; acc[3]  += w * k0.w;
            acc[4]  += w * k1.x; acc[5]  += w * k1.y; acc[6]  += w * k1.z; acc[7]  += w * k1.w;
            acc[8]  += w * k2.x; acc[9]  += w * k2.y; acc[10] += w * k2.z; acc[11] += w * k2.w;
            acc[12] += w * k3.x; acc[13] += w * k3.y; acc[14] += w * k3.z; acc[15] += w * k3.w;
        }
        __nv_bfloat16 hbuf[16], lbuf[16];
#pragma unroll
        for (int j = 0; j < 16; ++j) {
            __nv_bfloat16 hv = __float2bfloat16(acc[j]);
            hbuf[j] = hv;
            lbuf[j] = __float2bfloat16(acc[j] - __bfloat162float(hv));
        }
        int eo = n * PITCH + h * 32 + d0;
        uint4* dh = (uint4*)&g_G[br][0][eo];
        uint4* dl = (uint4*)&g_G[br][1][eo];
        dh[0] = ((uint4*)hbuf)[0]; dh[1] = ((uint4*)hbuf)[1];
        dl[0] = ((uint4*)lbuf)[0]; dl[1] = ((uint4*)lbuf)[1];
    }
}

// ---------------------------------------------------------------------------
// out: q = elu(x@Wq+bq) (in-CTA); z = 1/(q.ksum+eps);
//      out = sum_h z_h * (q_h @ G_h) + bo.  128-row tiles, 512 threads.
// ---------------------------------------------------------------------------
#define OA_HI 0
#define OA_LO 34816
#define OB_HI 69632
#define OB_LO 104448
#define OKS   139264            // ksum 128f
#define OZ    139776            // z 512f
#define OBQ   141824            // bq 128f
#define OBO   142336            // bo 128f
#define SMEM_OUT (OBO + 512)

__global__ __launch_bounds__(512, 1) void out_kernel(
    const float* __restrict__ x, const float* __restrict__ bq,
    const float* __restrict__ bo, float* __restrict__ out)
{
    extern __shared__ char smem[];
    const u32 sb = smem_u32(smem);
    const int tid = threadIdx.x;
    const int wid = tid >> 5;
    const int lane = tid & 31;
    const int g = lane >> 2, c = lane & 3;
    const size_t row0 = (size_t)blockIdx.x * 128;
    const int br = blockIdx.x >> 4;

    float* ks_s = (float*)(smem + OKS);
    float* zs   = (float*)(smem + OZ);
    float* bq_s = (float*)(smem + OBQ);
    float* bo_s = (float*)(smem + OBO);

    if (tid < 128) ks_s[tid] = g_ksum[(size_t)br * 128 + tid];
    else if (tid < 256) bq_s[tid - 128] = bq[tid - 128];
    else if (tid < 384) bo_s[tid - 256] = bo[tid - 256];

    // load x tile split into OA; Wq split into OB
    {
        const float4* xg = reinterpret_cast<const float4*>(x + row0 * EDIM);
#pragma unroll
        for (int i = 0; i < 8; ++i) {
            int idx = tid + i * 512;
            int row = idx >> 5;
            int c4  = (idx & 31) << 2;
            float4 v = xg[idx];
            u32 h01 = pack_bf2(v.x, v.y);
            u32 h23 = pack_bf2(v.z, v.w);
            u32 l01 = pack_bf2(v.x - bf_lo(h01), v.y - bf_hi(h01));
            u32 l23 = pack_bf2(v.z - bf_lo(h23), v.w - bf_hi(h23));
            int off = (row * PITCH + c4) * 2;
            *(uint2*)(smem + OA_HI + off) = make_uint2(h01, h23);
            *(uint2*)(smem + OA_LO + off) = make_uint2(l01, l23);
        }
        const uint4* gh = (const uint4*)g_wt[0][0];
        const uint4* gl = (const uint4*)g_wt[0][1];
        uint4* sh = (uint4*)(smem + OB_HI);
        uint4* sl = (uint4*)(smem + OB_LO);
#pragma unroll
        for (int i = 0; i < 5; ++i) {
            int idx = tid + i * 512;
            if (idx < 2176) { sh[idx] = gh[idx]; sl[idx] = gl[idx]; }
        }
    }
    __syncthreads();

    const int arow = (wid & 7) * 16;
    const int ncol0 = (wid >> 3) * 64;
    const u32 aHi = a_base(sb, OA_HI, arow, lane);
    const u32 aLo = a_base(sb, OA_LO, arow, lane);
    const u32 bHi = b_base(sb, OB_HI, ncol0, lane);
    const u32 bLo = b_base(sb, OB_LO, ncol0, lane);

    // q = x @ Wq (3-pass)
    float qa[8][4];
#pragma unroll
    for (int i = 0; i < 8; ++i)
#pragma unroll
        for (int j = 0; j < 4; ++j) qa[i][j] = 0.f;
    gemm3p_ldsm(aHi, aLo, bHi, bLo, qa);

    __syncthreads();   // all x reads (OA) + Wq reads (OB) done

    // bias + elu, split q fragments into OA
#pragma unroll
    for (int nt = 0; nt < 8; ++nt) {
        int col = ncol0 + nt * 8 + 2 * c;
        float2 bb = *(const float2*)(bq_s + col);
        float q0x = elu1(qa[nt][0] + bb.x), q0y = elu1(qa[nt][1] + bb.y);
        float q1x = elu1(qa[nt][2] + bb.x), q1y = elu1(qa[nt][3] + bb.y);
        u32 h0 = pack_bf2(q0x, q0y);
        u32 h1 = pack_bf2(q1x, q1y);
        u32 l0 = pack_bf2(q0x - bf_lo(h0), q0y - bf_hi(h0));
        u32 l1 = pack_bf2(q1x - bf_lo(h1), q1y - bf_hi(h1));
        int o0 = ((arow + g) * PITCH + col) * 2;
        int o1 = ((arow + g + 8) * PITCH + col) * 2;
        *(u32*)(smem + OA_HI + o0) = h0;
        *(u32*)(smem + OA_LO + o0) = l0;
        *(u32*)(smem + OA_HI + o1) = h1;
        *(u32*)(smem + OA_LO + o1) = l1;
    }

    // load G into OB (Wq dead)
    {
        const uint4* gh = (const uint4*)g_G[br][0];
        const uint4* gl = (const uint4*)g_G[br][1];
        uint4* sh = (uint4*)(smem + OB_HI);
        uint4* sl = (uint4*)(smem + OB_LO);
#pragma unroll
        for (int i = 0; i < 5; ++i) {
            int idx = tid + i * 512;
            if (idx < 2176) { sh[idx] = gh[idx]; sl[idx] = gl[idx]; }
        }
    }
    __syncthreads();   // q split + G ready

    // z per (row, head): 1 thread per pair, read split q from OA
    {
        const int row = tid >> 2;
        const int h   = tid & 3;
        const u32 bh0 = (u32)((row * PITCH + h * 32) * 2);
        const float* ksp = ks_s + h * 32;
        float dot = 0.f;
#pragma unroll
        for (int i = 0; i < 16; ++i) {
            u32 uh = *(const u32*)(smem + OA_HI + bh0 + i * 4);
            u32 ul = *(const u32*)(smem + OA_LO + bh0 + i * 4);
            dot += (bf_lo(uh) + bf_lo(ul)) * ksp[2 * i];
            dot += (bf_hi(uh) + bf_hi(ul)) * ksp[2 * i + 1];
        }
        zs[row * 4 + h] = 1.f / (dot + 1e-6f);
    }
    __syncthreads();

    // out = sum_h z_h * (q_h @ G_h) + bo
    {
        float acc[8][4];
#pragma unroll
        for (int i = 0; i < 8; ++i)
#pragma unroll
            for (int j = 0; j < 4; ++j) acc[i][j] = 0.f;

#pragma unroll
        for (int h = 0; h < 4; ++h) {
            float pacc[8][4];
#pragma unroll
            for (int i = 0; i < 8; ++i)
#pragma unroll
                for (int j = 0; j < 4; ++j) pacc[i][j] = 0.f;

#pragma unroll
            for (int ks = 0; ks < 2; ++ks) {
                const u32 koff = (u32)((h * 32 + ks * 16) * 2);
                u32 ah[4], al[4];
                ldsm_x4(ah, aHi + koff);
                ldsm_x4(al, aLo + koff);
#pragma unroll
                for (int np = 0; np < 4; ++np) {
                    const u32 boff = koff + (u32)(np * 16 * PITCH * 2);
                    u32 bh[4], bl[4];
                    ldsm_x4(bh, bHi + boff);
                    ldsm_x4(bl, bLo + boff);
                    mma16816(pacc[2 * np],     ah, bh[0], bh[1]);
                    mma16816(pacc[2 * np],     ah, bl[0], bl[1]);
                    mma16816(pacc[2 * np],     al, bh[0], bh[1]);
                    mma16816(pacc[2 * np + 1], ah, bh[2], bh[3]);
                    mma16816(pacc[2 * np + 1], ah, bl[2], bl[3]);
                    mma16816(pacc[2 * np + 1], al, bh[2], bh[3]);
                }
            }
            float z0 = zs[(arow + g) * 4 + h];
            float z1 = zs[(arow + g + 8) * 4 + h];
#pragma unroll
            for (int nt = 0; nt < 8; ++nt) {
                acc[nt][0] += z0 * pacc[nt][0];
                acc[nt][1] += z0 * pacc[nt][1];
                acc[nt][2] += z1 * pacc[nt][2];
                acc[nt][3] += z1 * pacc[nt][3];
            }
        }

#pragma unroll
        for (int nt = 0; nt < 8; ++nt) {
            int col = ncol0 + nt * 8 + 2 * c;
            float2 bb = *(const float2*)(bo_s + col);
            float2 r0, r1;
            r0.x = acc[nt][0] + bb.x; r0.y = acc[nt][1] + bb.y;
            r1.x = acc[nt][2] + bb.x; r1.y = acc[nt][3] + bb.y;
            size_t ra = row0 + arow + g;
            *(float2*)(out + ra * EDIM + col)       = r0;
            *(float2*)(out + (ra + 8) * EDIM + col) = r1;
        }
    }
}

// ---------------------------------------------------------------------------
extern "C" void kernel_launch(void* const* d_in, const int* in_sizes, int n_in,
                              void* d_out, int out_size)
{
    const float* x  = (const float*)d_in[0];
    const float* Wq = (const float*)d_in[1];
    const float* bq = (const float*)d_in[2];
    const float* Wk = (const float*)d_in[3];
    const float* bk = (const float*)d_in[4];
    const float* Wv = (const float*)d_in[5];
    const float* bv = (const float*)d_in[6];
    const float* Wo = (const float*)d_in[7];
    const float* bo = (const float*)d_in[8];
    float* out = (float*)d_out;

    cudaFuncSetAttribute(kv_kernel, cudaFuncAttributeMaxDynamicSharedMemorySize, SMEM_KV);
    cudaFuncSetAttribute(out_kernel, cudaFuncAttributeMaxDynamicSharedMemorySize, SMEM_OUT);

    wprep_kernel<<<3, 256>>>(Wq, Wk, Wv);
    kv_kernel<<<NCTA, 512, SMEM_KV>>>(x, bk, bv);
    fold_kernel<<<NBR * HEADS, 256>>>(Wo);
    out_kernel<<<NCTA, 512, SMEM_OUT>>>(x, bq, bo, out);
}